// round 1
// baseline (speedup 1.0000x reference)
#include <cuda_runtime.h>

// Problem constants: B=2, H=32, G=2048, C=2048, D=128, F=128
#define NPAIR 64           // B*H
#define GDIM  2048
#define CDIM  2048
#define NCAT  4096         // G + C
#define DDIM  128
#define FDIM  128

// Output layout (floats), reference return order:
// (heap_score_new, K_top_new, V_top_new, FK_top_new, H_sum, S_sum)
#define OFF_HEAP 0ULL
#define OFF_K    131072ULL      // 64*2048
#define OFF_V    16908288ULL    // + 64*2048*128
#define OFF_FK   33685504ULL
#define OFF_H    50462720ULL
#define OFF_S    51511296ULL    // + 64*128*128

#define CHUNKS  4
#define CHUNK_G 512            // CDIM / CHUNKS
#define KT      16             // k-tile rows per smem stage

// Scratch (no device allocation allowed -> __device__ globals)
__device__ unsigned int g_order[NPAIR * NCAT];                       // sorted indices per pair
__device__ float g_partH[(size_t)CHUNKS * NPAIR * FDIM * DDIM];      // 16 MB split-K partials
__device__ float g_partS[CHUNKS * NPAIR * FDIM];

// ---------------------------------------------------------------------------
// float -> monotone key helpers. Key high32 sorts ASCENDING <=> score DESCENDING.
// Ties broken by ascending original index (low32) = stable argsort(-score).
// ---------------------------------------------------------------------------
__device__ __forceinline__ unsigned int f2key_desc(float s) {
    unsigned int u = __float_as_uint(s);
    unsigned int us = (u & 0x80000000u) ? ~u : (u | 0x80000000u); // ascending map
    return ~us;                                                    // descending
}
__device__ __forceinline__ float key2f(unsigned int hi) {
    unsigned int us = ~hi;
    unsigned int u = (us & 0x80000000u) ? (us ^ 0x80000000u) : ~us;
    return __uint_as_float(u);
}

// ---------------------------------------------------------------------------
// Kernel 1: per-(b,h) full sort of 4096 (score,index) keys, bitonic in smem.
// Writes g_order and heap_score_new.
// ---------------------------------------------------------------------------
__global__ void __launch_bounds__(1024) sort_kernel(
    const float* __restrict__ heap_score,
    const float* __restrict__ win_score,
    float* __restrict__ out_heap)
{
    __shared__ unsigned long long keys[NCAT];   // 32 KB
    const int pair = blockIdx.x;
    const int tid  = threadIdx.x;

    #pragma unroll
    for (int t = 0; t < NCAT / 1024; ++t) {
        int p = tid + t * 1024;
        float s = (p < GDIM) ? heap_score[pair * GDIM + p]
                             : win_score[pair * CDIM + (p - GDIM)];
        keys[p] = ((unsigned long long)f2key_desc(s) << 32) | (unsigned int)p;
    }
    __syncthreads();

    for (int k = 2; k <= NCAT; k <<= 1) {
        for (int j = k >> 1; j > 0; j >>= 1) {
            #pragma unroll
            for (int t = 0; t < NCAT / 1024; ++t) {
                int i = tid + t * 1024;
                int l = i ^ j;
                if (l > i) {
                    unsigned long long a = keys[i];
                    unsigned long long b = keys[l];
                    bool up = ((i & k) == 0);
                    if ((a > b) == up) { keys[i] = b; keys[l] = a; }
                }
            }
            __syncthreads();
        }
    }

    #pragma unroll
    for (int t = 0; t < NCAT / 1024; ++t) {
        int p = tid + t * 1024;
        unsigned long long key = keys[p];
        g_order[pair * NCAT + p] = (unsigned int)key;
        if (p < GDIM)
            out_heap[pair * GDIM + p] = key2f((unsigned int)(key >> 32));
    }
}

// ---------------------------------------------------------------------------
// Kernel 2: gather top-G rows of K, V, FK. One warp per (row, array).
// ---------------------------------------------------------------------------
__global__ void __launch_bounds__(256) gather_kernel(
    const float* __restrict__ K_top, const float* __restrict__ V_top,
    const float* __restrict__ FK_top,
    const float* __restrict__ K_win, const float* __restrict__ V_win,
    const float* __restrict__ FK_win,
    float* __restrict__ out)
{
    const int gwarp = (blockIdx.x * blockDim.x + threadIdx.x) >> 5;
    const int lane  = threadIdx.x & 31;
    // total warps = NPAIR*GDIM*3 = 393216
    const int arr   = gwarp % 3;
    const int rowid = gwarp / 3;         // pair*GDIM + g
    const int pair  = rowid >> 11;
    const int g     = rowid & (GDIM - 1);

    const unsigned int idx = g_order[pair * NCAT + g];

    const float* top_arr = (arr == 0) ? K_top : (arr == 1) ? V_top : FK_top;
    const float* win_arr = (arr == 0) ? K_win : (arr == 1) ? V_win : FK_win;
    const unsigned long long off_dst =
        (arr == 0) ? OFF_K : (arr == 1) ? OFF_V : OFF_FK;

    const float* src = (idx < GDIM)
        ? top_arr + ((size_t)pair * GDIM + idx) * 128
        : win_arr + ((size_t)pair * CDIM + (idx - GDIM)) * 128;
    float* dst = out + off_dst + (size_t)rowid * 128;

    float4 v = ((const float4*)src)[lane];
    ((float4*)dst)[lane] = v;
}

// ---------------------------------------------------------------------------
// Kernel 3: H_sum[pair,f,d] = sum_g FK_bot[g,f] * V_bot[g,d];
//           S_sum[pair,f]   = sum_g FK_bot[g,f].
// Split-K over CHUNKS chunks of CHUNK_G rows, fp32 partials to scratch.
// Uses packed fma.rn.f32x2 (2x fp32 FMA rate on sm_103a).
// ---------------------------------------------------------------------------
__device__ __forceinline__ unsigned long long fma2(
    unsigned long long a, unsigned long long b, unsigned long long c)
{
    unsigned long long d;
    asm("fma.rn.f32x2 %0, %1, %2, %3;" : "=l"(d) : "l"(a), "l"(b), "l"(c));
    return d;
}
__device__ __forceinline__ unsigned long long pack2(float lo, float hi) {
    unsigned long long r;
    asm("mov.b64 %0, {%1, %2};" : "=l"(r) : "f"(lo), "f"(hi));
    return r;
}

__global__ void __launch_bounds__(256) gemm_kernel(
    const float* __restrict__ V_top, const float* __restrict__ FK_top,
    const float* __restrict__ V_win, const float* __restrict__ FK_win)
{
    __shared__ float FKs[KT][132];   // padded rows, 528 B stride (16B aligned)
    __shared__ float Vs [KT][132];
    __shared__ unsigned int idx_s[KT];

    const int pair  = blockIdx.x;
    const int chunk = blockIdx.y;
    const int tid   = threadIdx.x;
    const int tx    = tid & 15;      // d-tile index (8 d's each)
    const int ty    = tid >> 4;      // f-tile index (8 f's each)

    unsigned long long accp[8][4];   // 8 f x 8 d (as 4 packed pairs)
    float s_acc[8];
    #pragma unroll
    for (int i = 0; i < 8; ++i) {
        s_acc[i] = 0.0f;
        #pragma unroll
        for (int j = 0; j < 4; ++j) accp[i][j] = pack2(0.0f, 0.0f);
    }

    const int g0 = chunk * CHUNK_G;

    for (int kt = 0; kt < CHUNK_G / KT; ++kt) {
        __syncthreads();  // previous compute done with smem
        if (tid < KT)
            idx_s[tid] = g_order[pair * NCAT + GDIM + g0 + kt * KT + tid];
        __syncthreads();

        {   // tile load: thread-group ty loads row ty; 16 threads x 2 float4 per array
            const int r = ty;
            const unsigned int idx = idx_s[r];
            const float4* fsrc = (const float4*)((idx < GDIM)
                ? FK_top + ((size_t)pair * GDIM + idx) * FDIM
                : FK_win + ((size_t)pair * CDIM + (idx - GDIM)) * FDIM);
            const float4* vsrc = (const float4*)((idx < GDIM)
                ? V_top + ((size_t)pair * GDIM + idx) * DDIM
                : V_win + ((size_t)pair * CDIM + (idx - GDIM)) * DDIM);
            float4 a0 = fsrc[tx], a1 = fsrc[tx + 16];
            float4 b0 = vsrc[tx], b1 = vsrc[tx + 16];
            *(float4*)&FKs[r][tx * 4]        = a0;
            *(float4*)&FKs[r][(tx + 16) * 4] = a1;
            *(float4*)&Vs[r][tx * 4]         = b0;
            *(float4*)&Vs[r][(tx + 16) * 4]  = b1;
        }
        __syncthreads();

        #pragma unroll
        for (int kk = 0; kk < KT; ++kk) {
            float fv[8];
            *(float4*)&fv[0] = *(const float4*)&FKs[kk][ty * 8];
            *(float4*)&fv[4] = *(const float4*)&FKs[kk][ty * 8 + 4];
            unsigned long long vp[4];
            const unsigned long long* vrow =
                (const unsigned long long*)&Vs[kk][tx * 8];
            #pragma unroll
            for (int j = 0; j < 4; ++j) vp[j] = vrow[j];

            #pragma unroll
            for (int i = 0; i < 8; ++i) {
                unsigned long long fp = pack2(fv[i], fv[i]);
                #pragma unroll
                for (int j = 0; j < 4; ++j)
                    accp[i][j] = fma2(fp, vp[j], accp[i][j]);
            }
            if (tx == 0) {
                #pragma unroll
                for (int i = 0; i < 8; ++i) s_acc[i] += fv[i];
            }
        }
    }

    // write split-K partials (packed pairs are adjacent d's -> direct 8B store)
    float* Hp = g_partH + ((size_t)(chunk * NPAIR + pair)) * (FDIM * DDIM);
    #pragma unroll
    for (int i = 0; i < 8; ++i) {
        #pragma unroll
        for (int j = 0; j < 4; ++j) {
            *(unsigned long long*)&Hp[(ty * 8 + i) * DDIM + tx * 8 + j * 2] =
                accp[i][j];
        }
    }
    if (tx == 0) {
        float* Sp = g_partS + (chunk * NPAIR + pair) * FDIM;
        #pragma unroll
        for (int i = 0; i < 8; ++i) Sp[ty * 8 + i] = s_acc[i];
    }
}

// ---------------------------------------------------------------------------
// Kernel 4: deterministic split-K reduction into d_out.
// ---------------------------------------------------------------------------
__global__ void __launch_bounds__(256) reduce_kernel(float* __restrict__ out)
{
    const int NH = NPAIR * FDIM * DDIM;   // 1048576
    const int NS = NPAIR * FDIM;          // 8192
    int i = blockIdx.x * blockDim.x + threadIdx.x;
    if (i < NH) {
        float s = 0.0f;
        #pragma unroll
        for (int c = 0; c < CHUNKS; ++c) s += g_partH[(size_t)c * NH + i];
        out[OFF_H + i] = s;
    } else if (i < NH + NS) {
        int j = i - NH;
        float s = 0.0f;
        #pragma unroll
        for (int c = 0; c < CHUNKS; ++c) s += g_partS[c * NS + j];
        out[OFF_S + j] = s;
    }
}

// ---------------------------------------------------------------------------
extern "C" void kernel_launch(void* const* d_in, const int* in_sizes, int n_in,
                              void* d_out, int out_size)
{
    const float* K_top      = (const float*)d_in[0];
    const float* V_top      = (const float*)d_in[1];
    const float* FK_top     = (const float*)d_in[2];
    const float* heap_score = (const float*)d_in[3];
    const float* K_win      = (const float*)d_in[4];
    const float* V_win      = (const float*)d_in[5];
    const float* FK_win     = (const float*)d_in[6];
    const float* win_score  = (const float*)d_in[7];
    float* out = (float*)d_out;

    sort_kernel<<<NPAIR, 1024>>>(heap_score, win_score, out + OFF_HEAP);

    // NPAIR*GDIM*3 warps, 8 warps per block
    gather_kernel<<<(NPAIR * GDIM * 3) / 8, 256>>>(
        K_top, V_top, FK_top, K_win, V_win, FK_win, out);

    gemm_kernel<<<dim3(NPAIR, CHUNKS), 256>>>(V_top, FK_top, V_win, FK_win);

    const int NTOT = NPAIR * FDIM * DDIM + NPAIR * FDIM;
    reduce_kernel<<<(NTOT + 255) / 256, 256>>>(out);
}

// round 2
// speedup vs baseline: 1.0147x; 1.0147x over previous
#include <cuda_runtime.h>

// Problem constants: B=2, H=32, G=2048, C=2048, D=128, F=128
#define NPAIR 64
#define GDIM  2048
#define CDIM  2048
#define NCAT  4096
#define DDIM  128
#define FDIM  128

// Output layout (floats):
// (heap_score_new, K_top_new, V_top_new, FK_top_new, H_sum, S_sum)
#define OFF_HEAP 0ULL
#define OFF_K    131072ULL
#define OFF_V    16908288ULL
#define OFF_FK   33685504ULL
#define OFF_H    50462720ULL
#define OFF_S    51511296ULL

#define CHUNKS  8
#define CHUNK_G 256            // CDIM / CHUNKS
#define KT      16             // k-tile rows per smem stage

#define NGEMM_BLOCKS (NPAIR * CHUNKS)                 // 512
#define NGATHER_BLOCKS ((NPAIR * GDIM) / 8)           // 16384 (1 warp per row)

// Scratch (__device__ globals; no runtime allocation allowed)
__device__ unsigned int g_order[NPAIR * NCAT];
__device__ float g_partH[(size_t)CHUNKS * NPAIR * FDIM * DDIM];   // 32 MB
__device__ float g_partS[CHUNKS * NPAIR * FDIM];

// ---------------------------------------------------------------------------
// float -> monotone key. High32 ascending <=> score descending; ties by index.
// ---------------------------------------------------------------------------
__device__ __forceinline__ unsigned int f2key_desc(float s) {
    unsigned int u = __float_as_uint(s);
    unsigned int us = (u & 0x80000000u) ? ~u : (u | 0x80000000u);
    return ~us;
}
__device__ __forceinline__ float key2f(unsigned int hi) {
    unsigned int us = ~hi;
    unsigned int u = (us & 0x80000000u) ? (us ^ 0x80000000u) : ~us;
    return __uint_as_float(u);
}

// ---------------------------------------------------------------------------
// Kernel 1: per-(b,h) bitonic sort of 4096 (score,index) keys in smem.
// ---------------------------------------------------------------------------
__global__ void __launch_bounds__(1024) sort_kernel(
    const float* __restrict__ heap_score,
    const float* __restrict__ win_score,
    float* __restrict__ out_heap)
{
    __shared__ unsigned long long keys[NCAT];
    const int pair = blockIdx.x;
    const int tid  = threadIdx.x;

    #pragma unroll
    for (int t = 0; t < NCAT / 1024; ++t) {
        int p = tid + t * 1024;
        float s = (p < GDIM) ? heap_score[pair * GDIM + p]
                             : win_score[pair * CDIM + (p - GDIM)];
        keys[p] = ((unsigned long long)f2key_desc(s) << 32) | (unsigned int)p;
    }
    __syncthreads();

    for (int k = 2; k <= NCAT; k <<= 1) {
        for (int j = k >> 1; j > 0; j >>= 1) {
            #pragma unroll
            for (int t = 0; t < NCAT / 1024; ++t) {
                int i = tid + t * 1024;
                int l = i ^ j;
                if (l > i) {
                    unsigned long long a = keys[i];
                    unsigned long long b = keys[l];
                    bool up = ((i & k) == 0);
                    if ((a > b) == up) { keys[i] = b; keys[l] = a; }
                }
            }
            __syncthreads();
        }
    }

    #pragma unroll
    for (int t = 0; t < NCAT / 1024; ++t) {
        int p = tid + t * 1024;
        unsigned long long key = keys[p];
        g_order[pair * NCAT + p] = (unsigned int)key;
        if (p < GDIM)
            out_heap[pair * GDIM + p] = key2f((unsigned int)(key >> 32));
    }
}

// ---------------------------------------------------------------------------
// Packed fp32x2 FMA helpers
// ---------------------------------------------------------------------------
__device__ __forceinline__ unsigned long long fma2(
    unsigned long long a, unsigned long long b, unsigned long long c)
{
    unsigned long long d;
    asm("fma.rn.f32x2 %0, %1, %2, %3;" : "=l"(d) : "l"(a), "l"(b), "l"(c));
    return d;
}
__device__ __forceinline__ unsigned long long pack2(float lo, float hi) {
    unsigned long long r;
    asm("mov.b64 %0, {%1, %2};" : "=l"(r) : "f"(lo), "f"(hi));
    return r;
}

// ---------------------------------------------------------------------------
// Kernel 2 (fused): gemm CTAs (blockIdx < NGEMM_BLOCKS) + gather CTAs.
// Gemm: H_part[pair,f,d] over a 256-row chunk of the bottom set.
// Gather: one warp per top row; copies K, V, FK rows (shared index, MLP=3).
// ---------------------------------------------------------------------------
__global__ void __launch_bounds__(256, 2) fused_kernel(
    const float* __restrict__ K_top, const float* __restrict__ V_top,
    const float* __restrict__ FK_top,
    const float* __restrict__ K_win, const float* __restrict__ V_win,
    const float* __restrict__ FK_win,
    float* __restrict__ out)
{
    if (blockIdx.x < NGEMM_BLOCKS) {
        // ============================ GEMM ============================
        __shared__ float FKs[KT][132];
        __shared__ float Vs [KT][132];
        __shared__ unsigned int idx_s[KT];

        const int pair  = blockIdx.x & (NPAIR - 1);
        const int chunk = blockIdx.x >> 6;
        const int tid   = threadIdx.x;
        const int tx    = tid & 15;      // 8 d's each
        const int ty    = tid >> 4;      // 8 f's each

        unsigned long long accp[8][4];
        float s_acc[8];
        #pragma unroll
        for (int i = 0; i < 8; ++i) {
            s_acc[i] = 0.0f;
            #pragma unroll
            for (int j = 0; j < 4; ++j) accp[i][j] = pack2(0.0f, 0.0f);
        }

        const int g0 = chunk * CHUNK_G;

        for (int kt = 0; kt < CHUNK_G / KT; ++kt) {
            __syncthreads();
            if (tid < KT)
                idx_s[tid] = g_order[pair * NCAT + GDIM + g0 + kt * KT + tid];
            __syncthreads();

            {
                const int r = ty;
                const unsigned int idx = idx_s[r];
                const float4* fsrc = (const float4*)((idx < GDIM)
                    ? FK_top + ((size_t)pair * GDIM + idx) * FDIM
                    : FK_win + ((size_t)pair * CDIM + (idx - GDIM)) * FDIM);
                const float4* vsrc = (const float4*)((idx < GDIM)
                    ? V_top + ((size_t)pair * GDIM + idx) * DDIM
                    : V_win + ((size_t)pair * CDIM + (idx - GDIM)) * DDIM);
                float4 a0 = fsrc[tx], a1 = fsrc[tx + 16];
                float4 b0 = vsrc[tx], b1 = vsrc[tx + 16];
                *(float4*)&FKs[r][tx * 4]        = a0;
                *(float4*)&FKs[r][(tx + 16) * 4] = a1;
                *(float4*)&Vs[r][tx * 4]         = b0;
                *(float4*)&Vs[r][(tx + 16) * 4]  = b1;
            }
            __syncthreads();

            #pragma unroll
            for (int kk = 0; kk < KT; ++kk) {
                float fv[8];
                *(float4*)&fv[0] = *(const float4*)&FKs[kk][ty * 8];
                *(float4*)&fv[4] = *(const float4*)&FKs[kk][ty * 8 + 4];
                float4 va = *(const float4*)&Vs[kk][tx * 8];
                float4 vb = *(const float4*)&Vs[kk][tx * 8 + 4];
                unsigned long long vp[4];
                vp[0] = pack2(va.x, va.y);
                vp[1] = pack2(va.z, va.w);
                vp[2] = pack2(vb.x, vb.y);
                vp[3] = pack2(vb.z, vb.w);

                #pragma unroll
                for (int i = 0; i < 8; ++i) {
                    unsigned long long fp = pack2(fv[i], fv[i]);
                    #pragma unroll
                    for (int j = 0; j < 4; ++j)
                        accp[i][j] = fma2(fp, vp[j], accp[i][j]);
                }
                if (tx == 0) {
                    #pragma unroll
                    for (int i = 0; i < 8; ++i) s_acc[i] += fv[i];
                }
            }
        }

        float* Hp = g_partH + ((size_t)(chunk * NPAIR + pair)) * (FDIM * DDIM);
        #pragma unroll
        for (int i = 0; i < 8; ++i) {
            #pragma unroll
            for (int j = 0; j < 4; ++j) {
                *(unsigned long long*)&Hp[(ty * 8 + i) * DDIM + tx * 8 + j * 2]
                    = accp[i][j];
            }
        }
        if (tx == 0) {
            float* Sp = g_partS + (chunk * NPAIR + pair) * FDIM;
            #pragma unroll
            for (int i = 0; i < 8; ++i) Sp[ty * 8 + i] = s_acc[i];
        }
    } else {
        // =========================== GATHER ===========================
        const int gb    = blockIdx.x - NGEMM_BLOCKS;
        const int warp  = threadIdx.x >> 5;
        const int lane  = threadIdx.x & 31;
        const int rowid = gb * 8 + warp;          // pair*GDIM + g
        const int pair  = rowid >> 11;
        const int g     = rowid & (GDIM - 1);

        const unsigned int idx = g_order[pair * NCAT + g];

        const float4 *ksrc, *vsrc, *fsrc;
        if (idx < GDIM) {
            const size_t r = (size_t)pair * GDIM + idx;
            ksrc = (const float4*)(K_top  + r * 128);
            vsrc = (const float4*)(V_top  + r * 128);
            fsrc = (const float4*)(FK_top + r * 128);
        } else {
            const size_t r = (size_t)pair * CDIM + (idx - GDIM);
            ksrc = (const float4*)(K_win  + r * 128);
            vsrc = (const float4*)(V_win  + r * 128);
            fsrc = (const float4*)(FK_win + r * 128);
        }
        // issue all three loads before any store (MLP = 3)
        float4 kv = ksrc[lane];
        float4 vv = vsrc[lane];
        float4 fv = fsrc[lane];
        ((float4*)(out + OFF_K  + (size_t)rowid * 128))[lane] = kv;
        ((float4*)(out + OFF_V  + (size_t)rowid * 128))[lane] = vv;
        ((float4*)(out + OFF_FK + (size_t)rowid * 128))[lane] = fv;
    }
}

// ---------------------------------------------------------------------------
// Kernel 3: deterministic split-K reduction into d_out.
// ---------------------------------------------------------------------------
__global__ void __launch_bounds__(256) reduce_kernel(float* __restrict__ out)
{
    const int NH = NPAIR * FDIM * DDIM;   // 1048576
    const int NS = NPAIR * FDIM;          // 8192
    int i = blockIdx.x * blockDim.x + threadIdx.x;
    if (i < NH) {
        float s = 0.0f;
        #pragma unroll
        for (int c = 0; c < CHUNKS; ++c) s += g_partH[(size_t)c * NH + i];
        out[OFF_H + i] = s;
    } else if (i < NH + NS) {
        int j = i - NH;
        float s = 0.0f;
        #pragma unroll
        for (int c = 0; c < CHUNKS; ++c) s += g_partS[c * NS + j];
        out[OFF_S + j] = s;
    }
}

// ---------------------------------------------------------------------------
extern "C" void kernel_launch(void* const* d_in, const int* in_sizes, int n_in,
                              void* d_out, int out_size)
{
    const float* K_top      = (const float*)d_in[0];
    const float* V_top      = (const float*)d_in[1];
    const float* FK_top     = (const float*)d_in[2];
    const float* heap_score = (const float*)d_in[3];
    const float* K_win      = (const float*)d_in[4];
    const float* V_win      = (const float*)d_in[5];
    const float* FK_win     = (const float*)d_in[6];
    const float* win_score  = (const float*)d_in[7];
    float* out = (float*)d_out;

    sort_kernel<<<NPAIR, 1024>>>(heap_score, win_score, out + OFF_HEAP);

    fused_kernel<<<NGEMM_BLOCKS + NGATHER_BLOCKS, 256>>>(
        K_top, V_top, FK_top, K_win, V_win, FK_win, out);

    const int NTOT = NPAIR * FDIM * DDIM + NPAIR * FDIM;
    reduce_kernel<<<(NTOT + 255) / 256, 256>>>(out);
}

// round 3
// speedup vs baseline: 1.5239x; 1.5018x over previous
#include <cuda_runtime.h>

// B=2, H=32, G=2048, C=2048, D=128, F=128
#define NPAIR 64
#define GDIM  2048
#define CDIM  2048
#define NCAT  4096
#define DDIM  128
#define FDIM  128

// Output layout (floats):
#define OFF_HEAP 0ULL
#define OFF_K    131072ULL
#define OFF_V    16908288ULL
#define OFF_FK   33685504ULL
#define OFF_H    50462720ULL
#define OFF_S    51511296ULL

#define CHUNKS  4
#define CHUNK_G 512            // CDIM / CHUNKS
#define KT      16
#define NT      (CHUNK_G / KT) // 32 tiles

#define NGEMM_BLOCKS   (NPAIR * CHUNKS)            // 256
#define NGATHER_BLOCKS ((NPAIR * GDIM) / 16)       // 8192 (2 rows per warp)

typedef unsigned long long ull;

__device__ unsigned int g_order[NPAIR * NCAT];
__device__ float g_partH[(size_t)CHUNKS * NPAIR * FDIM * DDIM];   // 16 MB
__device__ float g_partS[CHUNKS * NPAIR * FDIM];

// ---------------------------------------------------------------------------
__device__ __forceinline__ unsigned int f2key_desc(float s) {
    unsigned int u = __float_as_uint(s);
    unsigned int us = (u & 0x80000000u) ? ~u : (u | 0x80000000u);
    return ~us;
}
__device__ __forceinline__ float key2f(unsigned int hi) {
    unsigned int us = ~hi;
    unsigned int u = (us & 0x80000000u) ? (us ^ 0x80000000u) : ~us;
    return __uint_as_float(u);
}
__device__ __forceinline__ void cswap(ull& a, ull& b, bool up) {
    if ((a > b) == up) { ull t = a; a = b; b = t; }
}

// ---------------------------------------------------------------------------
// Kernel 1: register-resident bitonic sort, 4 consecutive keys per thread.
// j<=2 in-thread; j=4..64 via shfl.xor; j>=128 via smem (15 barrier substages).
// ---------------------------------------------------------------------------
__global__ void __launch_bounds__(1024) sort_kernel(
    const float* __restrict__ heap_score,
    const float* __restrict__ win_score,
    float* __restrict__ out_heap)
{
    __shared__ ull sk[NCAT];   // 32 KB
    const int pair = blockIdx.x;
    const int tid  = threadIdx.x;

    // load 4 consecutive scores (vectorized)
    float4 sc;
    if (tid < 512) sc = ((const float4*)(heap_score + (size_t)pair * GDIM))[tid];
    else           sc = ((const float4*)(win_score  + (size_t)pair * CDIM))[tid - 512];

    ull e[4];
    {
        const int p = 4 * tid;
        e[0] = ((ull)f2key_desc(sc.x) << 32) | (unsigned)(p + 0);
        e[1] = ((ull)f2key_desc(sc.y) << 32) | (unsigned)(p + 1);
        e[2] = ((ull)f2key_desc(sc.z) << 32) | (unsigned)(p + 2);
        e[3] = ((ull)f2key_desc(sc.w) << 32) | (unsigned)(p + 3);
    }

    // k = 2
    cswap(e[0], e[1], true);
    cswap(e[2], e[3], false);

    for (int k = 4; k <= NCAT; k <<= 1) {
        const bool up = ((tid & (k >> 2)) == 0);
        for (int j = k >> 1; j >= 4; j >>= 1) {
            if (j >= 128) {
                // cross-warp: exchange whole 4-vectors through smem
                const int base = 4 * tid;
                sk[base + 0] = e[0]; sk[base + 1] = e[1];
                sk[base + 2] = e[2]; sk[base + 3] = e[3];
                __syncthreads();
                const int pt = (tid ^ (j >> 2)) * 4;
                const bool lower = ((tid & (j >> 2)) == 0);
                ull p0 = sk[pt], p1 = sk[pt + 1], p2 = sk[pt + 2], p3 = sk[pt + 3];
                if (lower == up) {
                    e[0] = e[0] < p0 ? e[0] : p0;  e[1] = e[1] < p1 ? e[1] : p1;
                    e[2] = e[2] < p2 ? e[2] : p2;  e[3] = e[3] < p3 ? e[3] : p3;
                } else {
                    e[0] = e[0] > p0 ? e[0] : p0;  e[1] = e[1] > p1 ? e[1] : p1;
                    e[2] = e[2] > p2 ? e[2] : p2;  e[3] = e[3] > p3 ? e[3] : p3;
                }
                __syncthreads();
            } else {
                // in-warp shuffle exchange
                const int w = j >> 2;
                const bool lower = ((tid & w) == 0);
                #pragma unroll
                for (int s = 0; s < 4; ++s) {
                    ull p = __shfl_xor_sync(0xffffffffu, e[s], w);
                    e[s] = (lower == up) ? (e[s] < p ? e[s] : p)
                                         : (e[s] > p ? e[s] : p);
                }
            }
        }
        // j = 2 and j = 1 (in-thread)
        cswap(e[0], e[2], up); cswap(e[1], e[3], up);
        cswap(e[0], e[1], up); cswap(e[2], e[3], up);
    }

    // store results
    {
        const int base = pair * NCAT + 4 * tid;
        g_order[base + 0] = (unsigned)e[0];
        g_order[base + 1] = (unsigned)e[1];
        g_order[base + 2] = (unsigned)e[2];
        g_order[base + 3] = (unsigned)e[3];
    }
    if (tid < 512) {
        float4 hs;
        hs.x = key2f((unsigned)(e[0] >> 32));
        hs.y = key2f((unsigned)(e[1] >> 32));
        hs.z = key2f((unsigned)(e[2] >> 32));
        hs.w = key2f((unsigned)(e[3] >> 32));
        ((float4*)(out_heap + (size_t)pair * GDIM))[tid] = hs;
    }
}

// ---------------------------------------------------------------------------
// Packed fp32x2 helpers
// ---------------------------------------------------------------------------
__device__ __forceinline__ ull fma2(ull a, ull b, ull c) {
    ull d;
    asm("fma.rn.f32x2 %0, %1, %2, %3;" : "=l"(d) : "l"(a), "l"(b), "l"(c));
    return d;
}
__device__ __forceinline__ ull pack2(float lo, float hi) {
    ull r;
    asm("mov.b64 %0, {%1, %2};" : "=l"(r) : "f"(lo), "f"(hi));
    return r;
}
__device__ __forceinline__ void cp16(void* smem_dst, const void* gsrc) {
    unsigned s = (unsigned)__cvta_generic_to_shared(smem_dst);
    asm volatile("cp.async.cg.shared.global [%0], [%1], 16;\n" :: "r"(s), "l"(gsrc));
}

// ---------------------------------------------------------------------------
// Kernel 2 (fused): gemm CTAs first, gather CTAs fill the rest.
// ---------------------------------------------------------------------------
__global__ void __launch_bounds__(256, 2) fused_kernel(
    const float* __restrict__ K_top, const float* __restrict__ V_top,
    const float* __restrict__ FK_top,
    const float* __restrict__ K_win, const float* __restrict__ V_win,
    const float* __restrict__ FK_win,
    float* __restrict__ out)
{
    __shared__ float FKs[2][KT][FDIM];   // 16 KB
    __shared__ float Vs [2][KT][DDIM];   // 16 KB

    if (blockIdx.x < NGEMM_BLOCKS) {
        // ============================ GEMM ============================
        const int pair  = blockIdx.x & (NPAIR - 1);
        const int chunk = blockIdx.x >> 6;
        const int tid   = threadIdx.x;
        const int tx    = tid & 15;      // d chunks: tx*4 and 64+tx*4
        const int ty    = tid >> 4;      // f: ty*8 .. ty*8+7; also row loader id
        const int g0    = chunk * CHUNK_G;
        const int obase = pair * NCAT + GDIM + g0;

        ull accp[8][4];
        float s_acc[8];
        #pragma unroll
        for (int i = 0; i < 8; ++i) {
            s_acc[i] = 0.0f;
            #pragma unroll
            for (int j = 0; j < 4; ++j) accp[i][j] = pack2(0.0f, 0.0f);
        }

        // tile issue: row ty, 4 x 16B per thread via cp.async
        auto issue_tile = [&](int kt, int buf) {
            const unsigned idx = g_order[obase + kt * KT + ty];
            const float *fsrc, *vsrc;
            if (idx < GDIM) {
                const size_t r = (size_t)pair * GDIM + idx;
                fsrc = FK_top + r * FDIM;  vsrc = V_top + r * DDIM;
            } else {
                const size_t r = (size_t)pair * CDIM + (idx - GDIM);
                fsrc = FK_win + r * FDIM;  vsrc = V_win + r * DDIM;
            }
            cp16(&FKs[buf][ty][tx * 4],        fsrc + tx * 4);
            cp16(&FKs[buf][ty][(tx + 16) * 4], fsrc + (tx + 16) * 4);
            cp16(&Vs [buf][ty][tx * 4],        vsrc + tx * 4);
            cp16(&Vs [buf][ty][(tx + 16) * 4], vsrc + (tx + 16) * 4);
        };

        issue_tile(0, 0);
        asm volatile("cp.async.commit_group;\n");

        for (int kt = 0; kt < NT; ++kt) {
            const int buf = kt & 1;
            if (kt + 1 < NT) {
                issue_tile(kt + 1, buf ^ 1);
                asm volatile("cp.async.commit_group;\n");
                asm volatile("cp.async.wait_group 1;\n");
            } else {
                asm volatile("cp.async.wait_group 0;\n");
            }
            __syncthreads();

            #pragma unroll
            for (int kk = 0; kk < KT; ++kk) {
                float fv[8];
                *(float4*)&fv[0] = *(const float4*)&FKs[buf][kk][ty * 8];
                *(float4*)&fv[4] = *(const float4*)&FKs[buf][kk][ty * 8 + 4];
                float4 va = *(const float4*)&Vs[buf][kk][tx * 4];
                float4 vb = *(const float4*)&Vs[buf][kk][64 + tx * 4];
                ull vp[4];
                vp[0] = pack2(va.x, va.y);
                vp[1] = pack2(va.z, va.w);
                vp[2] = pack2(vb.x, vb.y);
                vp[3] = pack2(vb.z, vb.w);

                #pragma unroll
                for (int i = 0; i < 8; ++i) {
                    ull fp = pack2(fv[i], fv[i]);
                    #pragma unroll
                    for (int j = 0; j < 4; ++j)
                        accp[i][j] = fma2(fp, vp[j], accp[i][j]);
                }
                if (tx == 0) {
                    #pragma unroll
                    for (int i = 0; i < 8; ++i) s_acc[i] += fv[i];
                }
            }
            __syncthreads();
        }

        float* Hp = g_partH + ((size_t)(chunk * NPAIR + pair)) * (FDIM * DDIM);
        #pragma unroll
        for (int i = 0; i < 8; ++i) {
            const int f = ty * 8 + i;
            *(ull*)&Hp[f * DDIM + tx * 4]          = accp[i][0];
            *(ull*)&Hp[f * DDIM + tx * 4 + 2]      = accp[i][1];
            *(ull*)&Hp[f * DDIM + 64 + tx * 4]     = accp[i][2];
            *(ull*)&Hp[f * DDIM + 64 + tx * 4 + 2] = accp[i][3];
        }
        if (tx == 0) {
            float* Sp = g_partS + (chunk * NPAIR + pair) * FDIM;
            #pragma unroll
            for (int i = 0; i < 8; ++i) Sp[ty * 8 + i] = s_acc[i];
        }
    } else {
        // =========================== GATHER ===========================
        const int gb   = blockIdx.x - NGEMM_BLOCKS;
        const int warp = threadIdx.x >> 5;
        const int lane = threadIdx.x & 31;
        const int rowid0 = (gb * 8 + warp) * 2;     // two consecutive rows
        const int pair   = rowid0 >> 11;
        const int g      = rowid0 & (GDIM - 1);

        const unsigned idx0 = g_order[pair * NCAT + g];
        const unsigned idx1 = g_order[pair * NCAT + g + 1];

        const float4 *k0, *v0, *f0, *k1, *v1, *f1;
        if (idx0 < GDIM) {
            const size_t r = (size_t)pair * GDIM + idx0;
            k0 = (const float4*)(K_top + r * 128);
            v0 = (const float4*)(V_top + r * 128);
            f0 = (const float4*)(FK_top + r * 128);
        } else {
            const size_t r = (size_t)pair * CDIM + (idx0 - GDIM);
            k0 = (const float4*)(K_win + r * 128);
            v0 = (const float4*)(V_win + r * 128);
            f0 = (const float4*)(FK_win + r * 128);
        }
        if (idx1 < GDIM) {
            const size_t r = (size_t)pair * GDIM + idx1;
            k1 = (const float4*)(K_top + r * 128);
            v1 = (const float4*)(V_top + r * 128);
            f1 = (const float4*)(FK_top + r * 128);
        } else {
            const size_t r = (size_t)pair * CDIM + (idx1 - GDIM);
            k1 = (const float4*)(K_win + r * 128);
            v1 = (const float4*)(V_win + r * 128);
            f1 = (const float4*)(FK_win + r * 128);
        }
        // 6 independent loads in flight per lane
        float4 a = k0[lane], b = v0[lane], c = f0[lane];
        float4 d = k1[lane], e = v1[lane], f = f1[lane];
        ((float4*)(out + OFF_K  + (size_t)rowid0 * 128))[lane]       = a;
        ((float4*)(out + OFF_V  + (size_t)rowid0 * 128))[lane]       = b;
        ((float4*)(out + OFF_FK + (size_t)rowid0 * 128))[lane]       = c;
        ((float4*)(out + OFF_K  + (size_t)(rowid0 + 1) * 128))[lane] = d;
        ((float4*)(out + OFF_V  + (size_t)(rowid0 + 1) * 128))[lane] = e;
        ((float4*)(out + OFF_FK + (size_t)(rowid0 + 1) * 128))[lane] = f;
    }
}

// ---------------------------------------------------------------------------
// Kernel 3: deterministic split-K reduction.
// ---------------------------------------------------------------------------
__global__ void __launch_bounds__(256) reduce_kernel(float* __restrict__ out)
{
    const int NH = NPAIR * FDIM * DDIM;   // 1048576
    const int NS = NPAIR * FDIM;          // 8192
    int i = blockIdx.x * blockDim.x + threadIdx.x;
    if (i < NH) {
        float s = 0.0f;
        #pragma unroll
        for (int c = 0; c < CHUNKS; ++c) s += g_partH[(size_t)c * NH + i];
        out[OFF_H + i] = s;
    } else if (i < NH + NS) {
        int j = i - NH;
        float s = 0.0f;
        #pragma unroll
        for (int c = 0; c < CHUNKS; ++c) s += g_partS[c * NS + j];
        out[OFF_S + j] = s;
    }
}

// ---------------------------------------------------------------------------
extern "C" void kernel_launch(void* const* d_in, const int* in_sizes, int n_in,
                              void* d_out, int out_size)
{
    const float* K_top      = (const float*)d_in[0];
    const float* V_top      = (const float*)d_in[1];
    const float* FK_top     = (const float*)d_in[2];
    const float* heap_score = (const float*)d_in[3];
    const float* K_win      = (const float*)d_in[4];
    const float* V_win      = (const float*)d_in[5];
    const float* FK_win     = (const float*)d_in[6];
    const float* win_score  = (const float*)d_in[7];
    float* out = (float*)d_out;

    sort_kernel<<<NPAIR, 1024>>>(heap_score, win_score, out + OFF_HEAP);

    fused_kernel<<<NGEMM_BLOCKS + NGATHER_BLOCKS, 256>>>(
        K_top, V_top, FK_top, K_win, V_win, FK_win, out);

    const int NTOT = NPAIR * FDIM * DDIM + NPAIR * FDIM;
    reduce_kernel<<<(NTOT + 255) / 256, 256>>>(out);
}